// round 13
// baseline (speedup 1.0000x reference)
#include <cuda_runtime.h>
#include <cuda_fp16.h>
#include <math.h>

#define NN   8192
#define BB   16
#define IND  2
#define HH   64
#define FF   66
#define EE   131072
#define NMAT 5
#define KP   72
#define SROW 1024     // 16 batches * 64 halves = 2048 B
#define SV4  128      // uint4 per state row
#define IROW 32       // 16 batches * 2 halves = 64 B
#define INBLK (NN/32) // input-part spmm blocks
#define CNT_BLKS (EE/4/256)                 // 128
// init work in uint4 (8-half) units
#define I_T1 ((size_t)NN*SROW/8)
#define I_T2 (I_T1 + (size_t)NN*IROW/8)
#define I_T3 (I_T2 + (size_t)NMAT*128*KP/8)
#define I_T4 (I_T3 + (size_t)NMAT*64*KP/8)
#define INIT_BLKS ((unsigned)((I_T4 + 255)/256))
#define SCW_MAX 512   // smem-staged edges per row

// ---------------- device scratch (static; zero-initialized at load) ----------
__device__ __half g_Xs[(size_t)10*NN*SROW];
__device__ __half g_Xin[(size_t)5*NN*IROW];
__device__ __half g_U[(size_t)BB*NN*HH];
__device__ __half g_Wg_h[NMAT*128*KP];
__device__ __half g_Wc_h[NMAT*64*KP];
__device__ int   g_cnt[2][NN];     // zeroed by k_sortfill each call
__device__ int   g_cur[2][NN];     // zeroed by k_sortfill each call
__device__ int   g_ptr[2][NN+1];
__device__ int   g_eidx[2][EE];
__device__ int2  g_cw[2][EE];
__device__ int   g_done;           // scan ticket; reset by scanning block

// ---------------- helpers ------------------------------------------------------
__device__ __forceinline__ uint4 pack8(const float* a)
{
    __half2 a0 = __floats2half2_rn(a[0],a[1]);
    __half2 a1 = __floats2half2_rn(a[2],a[3]);
    __half2 a2 = __floats2half2_rn(a[4],a[5]);
    __half2 a3 = __floats2half2_rn(a[6],a[7]);
    uint4 st; st.x=*(unsigned*)&a0; st.y=*(unsigned*)&a1; st.z=*(unsigned*)&a2; st.w=*(unsigned*)&a3;
    return st;
}

// ---------------- fused count + init (8x vectorized) + last-block scan --------
__global__ void k_count_init(const int* __restrict__ src, const int* __restrict__ dst,
                             const float* __restrict__ inputs, const float* __restrict__ state,
                             const float* __restrict__ Wg, const float* __restrict__ Wc)
{
    if (blockIdx.x < CNT_BLKS) {
        int e4 = blockIdx.x*blockDim.x + threadIdx.x;
        int4 s = __ldg((const int4*)src + e4);
        int4 d = __ldg((const int4*)dst + e4);
        atomicAdd(&g_cnt[0][s.x], 1); atomicAdd(&g_cnt[0][s.y], 1);
        atomicAdd(&g_cnt[0][s.z], 1); atomicAdd(&g_cnt[0][s.w], 1);
        atomicAdd(&g_cnt[1][d.x], 1); atomicAdd(&g_cnt[1][d.y], 1);
        atomicAdd(&g_cnt[1][d.z], 1); atomicAdd(&g_cnt[1][d.w], 1);

        // last count block to finish performs the prefix scan
        __threadfence();
        __syncthreads();
        __shared__ int ticket;
        if (threadIdx.x == 0) ticket = atomicAdd(&g_done, 1);
        __syncthreads();
        if (ticket != CNT_BLKS-1) return;

        __shared__ int wsum[8];
        int tid = threadIdx.x, lane = tid & 31, wrp = tid >> 5;
        for (int m = 0; m < 2; m++) {
            int base = tid*32;
            int c[32];
            int s_local = 0;
            #pragma unroll
            for (int j = 0; j < 32; j++) { c[j] = __ldcg(&g_cnt[m][base+j]); s_local += c[j]; }
            int v = s_local;
            #pragma unroll
            for (int off = 1; off < 32; off <<= 1) {
                int o = __shfl_up_sync(0xffffffffu, v, off);
                if (lane >= off) v += o;
            }
            if (lane == 31) wsum[wrp] = v;
            __syncthreads();
            if (wrp == 0) {
                int w = (lane < 8) ? wsum[lane] : 0;
                #pragma unroll
                for (int off = 1; off < 8; off <<= 1) {
                    int o = __shfl_up_sync(0xffffffffu, w, off);
                    if (lane >= off) w += o;
                }
                if (lane < 8) wsum[lane] = w;
            }
            __syncthreads();
            int run = v - s_local + (wrp ? wsum[wrp-1] : 0);
            #pragma unroll
            for (int j = 0; j < 32; j++) { g_ptr[m][base+j] = run; run += c[j]; }
            if (tid == 255) g_ptr[m][NN] = run;
            __syncthreads();
        }
        if (tid == 0) g_done = 0;
        return;
    }

    size_t idx = (size_t)(blockIdx.x - CNT_BLKS)*blockDim.x + threadIdx.x;
    if (idx < I_T1) {
        size_t h8 = idx*8;
        int n = (int)(h8 / SROW);
        int c = (int)(h8 - (size_t)n*SROW);
        int b = c >> 6, h0 = c & 63;
        const float4* sp = (const float4*)(state + (size_t)b*NN*HH + (size_t)n*HH + h0);
        float4 f0 = __ldg(sp), f1 = __ldg(sp+1);
        float v[8] = {f0.x,f0.y,f0.z,f0.w,f1.x,f1.y,f1.z,f1.w};
        ((uint4*)g_Xs)[idx] = pack8(v);
    } else if (idx < I_T2) {
        size_t i8 = (idx - I_T1)*8;
        int n = (int)(i8 / IROW);
        int c0 = (int)(i8 - (size_t)n*IROW);
        int b0 = c0 >> 1;
        float v[8];
        #pragma unroll
        for (int u = 0; u < 4; u++) {
            float2 p = *(const float2*)(inputs + (size_t)(b0+u)*NN*IND + (size_t)n*IND);
            v[2*u] = p.x; v[2*u+1] = p.y;
        }
        ((uint4*)g_Xin)[idx - I_T1] = pack8(v);
    } else if (idx < I_T3) {
        size_t i8 = (idx - I_T2)*8;
        int m = (int)(i8 / (128*KP));
        int rem = (int)(i8 - (size_t)m*(128*KP));
        int o = rem / KP, k0 = rem - o*KP;
        float v[8];
        #pragma unroll
        for (int u = 0; u < 8; u++) {
            int k = k0 + u;
            float w = 0.f;
            if (k < 66) {
                int f = (k < 64) ? (k + IND) : (k - 64);
                const float* base = Wg + (size_t)(f*NMAT)*128 + o;
                if      (m == 0) w = base[0] - base[2*128] - base[4*128];
                else if (m == 2) w = 2.f*base[2*128];
                else if (m == 4) w = 2.f*base[4*128];
                else             w = base[m*128];
            }
            v[u] = w;
        }
        ((uint4*)g_Wg_h)[idx - I_T2] = pack8(v);
    } else if (idx < I_T4) {
        size_t i8 = (idx - I_T3)*8;
        int m = (int)(i8 / (64*KP));
        int rem = (int)(i8 - (size_t)m*(64*KP));
        int o = rem / KP, k0 = rem - o*KP;
        float v[8];
        #pragma unroll
        for (int u = 0; u < 8; u++) {
            int k = k0 + u;
            float w = 0.f;
            if (k < 66) {
                int f = (k < 64) ? (k + IND) : (k - 64);
                const float* base = Wc + (size_t)(f*NMAT)*64 + o;
                if      (m == 0) w = base[0] - base[2*64] - base[4*64];
                else if (m == 2) w = 2.f*base[2*64];
                else if (m == 4) w = 2.f*base[4*64];
                else             w = base[m*64];
            }
            v[u] = w;
        }
        ((uint4*)g_Wc_h)[idx - I_T3] = pack8(v);
    }
}

__global__ void k_scatter(const int* __restrict__ src, const int* __restrict__ dst)
{
    int e4 = blockIdx.x*blockDim.x + threadIdx.x;
    if (e4 < EE/4) {
        int4 s = __ldg((const int4*)src + e4);
        int4 d = __ldg((const int4*)dst + e4);
        int e = e4*4;
        int p;
        p = g_ptr[0][s.x] + atomicAdd(&g_cur[0][s.x], 1); g_eidx[0][p] = e;
        p = g_ptr[0][s.y] + atomicAdd(&g_cur[0][s.y], 1); g_eidx[0][p] = e+1;
        p = g_ptr[0][s.z] + atomicAdd(&g_cur[0][s.z], 1); g_eidx[0][p] = e+2;
        p = g_ptr[0][s.w] + atomicAdd(&g_cur[0][s.w], 1); g_eidx[0][p] = e+3;
        p = g_ptr[1][d.x] + atomicAdd(&g_cur[1][d.x], 1); g_eidx[1][p] = e;
        p = g_ptr[1][d.y] + atomicAdd(&g_cur[1][d.y], 1); g_eidx[1][p] = e+1;
        p = g_ptr[1][d.z] + atomicAdd(&g_cur[1][d.z], 1); g_eidx[1][p] = e+2;
        p = g_ptr[1][d.w] + atomicAdd(&g_cur[1][d.w], 1); g_eidx[1][p] = e+3;
    }
}

// ---- warp-per-row bitonic sort (64 elems) + fill + counter cleanup -----------
__global__ void k_sortfill(const int* __restrict__ src, const int* __restrict__ dst,
                           const float* __restrict__ v1, const float* __restrict__ v2)
{
    int m    = blockIdx.y;
    int wrp  = threadIdx.x >> 5;
    int lane = threadIdx.x & 31;
    int r    = blockIdx.x*8 + wrp;
    if (r >= NN) return;
    int beg = g_ptr[m][r], end = g_ptr[m][r+1];
    int deg = end - beg;

    if (lane == 0) { g_cnt[m][r] = 0; g_cur[m][r] = 0; }

    if (deg <= 64) {
        const int BIG = 0x7fffffff;
        int e0 = (lane      < deg) ? g_eidx[m][beg + lane]      : BIG;
        int e1 = (lane + 32 < deg) ? g_eidx[m][beg + lane + 32] : BIG;

        #pragma unroll
        for (int k = 2; k <= 64; k <<= 1) {
            #pragma unroll
            for (int j = k >> 1; j > 0; j >>= 1) {
                if (j == 32) {
                    int lo = min(e0, e1), hi = max(e0, e1);
                    e0 = lo; e1 = hi;
                } else {
                    int p0 = __shfl_xor_sync(0xffffffffu, e0, j);
                    bool up0 = ((lane & k) == 0) || (k == 64);
                    bool km0 = (((lane & j) == 0) == up0);
                    e0 = km0 ? min(e0, p0) : max(e0, p0);
                    int p1 = __shfl_xor_sync(0xffffffffu, e1, j);
                    bool up1 = (k == 64) || (((lane + 32) & k) == 0);
                    bool km1 = (((lane & j) == 0) == up1);
                    e1 = km1 ? min(e1, p1) : max(e1, p1);
                }
            }
        }
        if (lane < deg) {
            int e = e0;
            int2 cw;
            if (m == 0) { cw.x = __ldg(dst+e); cw.y = __float_as_int(__ldg(v1+e)); }
            else        { cw.x = __ldg(src+e); cw.y = __float_as_int(__ldg(v2+e)); }
            g_cw[m][beg + lane] = cw;
        }
        if (lane + 32 < deg) {
            int e = e1;
            int2 cw;
            if (m == 0) { cw.x = __ldg(dst+e); cw.y = __float_as_int(__ldg(v1+e)); }
            else        { cw.x = __ldg(src+e); cw.y = __float_as_int(__ldg(v2+e)); }
            g_cw[m][beg + lane + 32] = cw;
        }
    } else if (lane == 0) {
        for (int i = beg+1; i < end; i++) {
            int key = g_eidx[m][i];
            int j = i-1;
            while (j >= beg && g_eidx[m][j] > key) { g_eidx[m][j+1] = g_eidx[m][j]; j--; }
            g_eidx[m][j+1] = key;
        }
        for (int i = beg; i < end; i++) {
            int e = g_eidx[m][i];
            int2 cw;
            if (m == 0) { cw.x = dst[e]; cw.y = __float_as_int(v1[e]); }
            else        { cw.x = src[e]; cw.y = __float_as_int(v2[e]); }
            g_cw[m][i] = cw;
        }
    }
}

// ---------------- SPMM: Y = A_m X (smem-staged edge list) --------------------
__device__ __forceinline__ void acc8(float* a, float w, uint4 h)
{
    float2 p0 = __half22float2(*(const __half2*)&h.x);
    float2 p1 = __half22float2(*(const __half2*)&h.y);
    float2 p2 = __half22float2(*(const __half2*)&h.z);
    float2 p3 = __half22float2(*(const __half2*)&h.w);
    a[0] += w*p0.x; a[1] += w*p0.y; a[2] += w*p1.x; a[3] += w*p1.y;
    a[4] += w*p2.x; a[5] += w*p2.y; a[6] += w*p3.x; a[7] += w*p3.y;
}

__global__ void __launch_bounds__(128) k_spmm(int xiA,int yiA,int xiB,int yiB)
{
    __shared__ int2 scw[SCW_MAX];
    int m  = blockIdx.y;
    int xi = m ? xiB : xiA;
    int yi = m ? yiB : yiA;
    const int2* __restrict__ cw = g_cw[m];

    if (blockIdx.x < NN) {
        const uint4* __restrict__ X = (const uint4*)(g_Xs + (size_t)xi*NN*SROW);
        uint4*       __restrict__ Y = (uint4*)      (g_Xs + (size_t)yi*NN*SROW);
        int r = blockIdx.x;
        int t = threadIdx.x;
        int beg = g_ptr[m][r], end = g_ptr[m][r+1];
        int deg = end - beg;
        int nds = min(deg, SCW_MAX);

        for (int i = t; i < nds; i += 128) scw[i] = __ldg(cw + beg + i);
        __syncthreads();

        float acc[8] = {0.f,0.f,0.f,0.f,0.f,0.f,0.f,0.f};
        int j = 0;
        for (; j + 8 <= nds; j += 8) {
            int2 e[8];
            #pragma unroll
            for (int u = 0; u < 8; u++) e[u] = scw[j+u];
            uint4 h[8];
            #pragma unroll
            for (int u = 0; u < 8; u++) h[u] = __ldg(X + (size_t)e[u].x*SV4 + t);
            #pragma unroll
            for (int u = 0; u < 8; u++) acc8(acc, __int_as_float(e[u].y), h[u]);
        }
        for (; j < nds; j++) {
            int2 e = scw[j];
            uint4 h = __ldg(X + (size_t)e.x*SV4 + t);
            acc8(acc, __int_as_float(e.y), h);
        }
        for (int jj = beg + nds; jj < end; jj++) {   // rare overflow path
            int2 e = __ldg(cw + jj);
            uint4 h = __ldg(X + (size_t)e.x*SV4 + t);
            acc8(acc, __int_as_float(e.y), h);
        }
        Y[(size_t)r*SV4 + t] = pack8(acc);
    } else {
        const uint4* __restrict__ X = (const uint4*)(g_Xin + (size_t)xi*NN*IROW);
        uint4*       __restrict__ Y = (uint4*)      (g_Xin + (size_t)yi*NN*IROW);
        int r = (blockIdx.x - NN)*32 + (threadIdx.x >> 2);
        int q = threadIdx.x & 3;
        int beg = g_ptr[m][r], end = g_ptr[m][r+1];
        float acc[8] = {0.f,0.f,0.f,0.f,0.f,0.f,0.f,0.f};
        for (int j = beg; j < end; j++) {
            int2 e = __ldg(cw + j);
            uint4 h = __ldg(X + (size_t)e.x*4 + q);
            acc8(acc, __int_as_float(e.y), h);
        }
        Y[(size_t)r*4 + q] = pack8(acc);
    }
}

// ---------------- MMA / ldmatrix helpers --------------------------------------
__device__ __forceinline__ void mma_16816(float c[4], const unsigned a[4], const unsigned b[2]) {
    asm volatile(
        "mma.sync.aligned.m16n8k16.row.col.f32.f16.f16.f32 "
        "{%0,%1,%2,%3},{%4,%5,%6,%7},{%8,%9},{%0,%1,%2,%3};\n"
        : "+f"(c[0]), "+f"(c[1]), "+f"(c[2]), "+f"(c[3])
        : "r"(a[0]), "r"(a[1]), "r"(a[2]), "r"(a[3]), "r"(b[0]), "r"(b[1]));
}
__device__ __forceinline__ void mma_1688(float c[4], const unsigned a[2], const unsigned b0) {
    asm volatile(
        "mma.sync.aligned.m16n8k8.row.col.f32.f16.f16.f32 "
        "{%0,%1,%2,%3},{%4,%5},{%6},{%0,%1,%2,%3};\n"
        : "+f"(c[0]), "+f"(c[1]), "+f"(c[2]), "+f"(c[3])
        : "r"(a[0]), "r"(a[1]), "r"(b0));
}
__device__ __forceinline__ unsigned su32(const void* p) {
    return (unsigned)__cvta_generic_to_shared(p);
}
__device__ __forceinline__ void ldsm4(unsigned* r, unsigned a) {
    asm volatile("ldmatrix.sync.aligned.m8n8.x4.shared.b16 {%0,%1,%2,%3},[%4];"
        : "=r"(r[0]),"=r"(r[1]),"=r"(r[2]),"=r"(r[3]) : "r"(a));
}
__device__ __forceinline__ void ldsm2(unsigned* r, unsigned a) {
    asm volatile("ldmatrix.sync.aligned.m8n8.x2.shared.b16 {%0,%1},[%2];"
        : "=r"(r[0]),"=r"(r[1]) : "r"(a));
}

// ---------------- gate GEMM (pipelined tile loads) + fused gating -------------
__global__ void __launch_bounds__(256) k_gemm_gate(const float* __restrict__ bg,
                                                   const float* __restrict__ state)
{
    __shared__ __align__(16) __half As[128][KP];
    __shared__ __align__(16) __half Bs[128][KP];

    int row0 = blockIdx.x * 128;
    int b  = row0 / NN;
    int n0 = row0 - b*NN;
    int tid = threadIdx.x;
    int wid = tid >> 5, lane = tid & 31;
    int q = lane & 3, rr_ = lane >> 2;
    int warp_m = wid & 3, warp_n = wid >> 2;

    unsigned Au[2], At[2], Bu[4], Bt[4];
    #pragma unroll
    for (int mt = 0; mt < 2; mt++) {
        Au[mt] = su32(&As[warp_m*32 + mt*16 + (lane & 15)][(lane >> 4)*8]);
        At[mt] = su32(&As[warp_m*32 + mt*16 + (lane & 15)][64]);
    }
    #pragma unroll
    for (int p = 0; p < 4; p++) {
        Bu[p] = su32(&Bs[warp_n*64 + p*16 + (lane & 7) + ((lane >> 4) & 1)*8][((lane >> 3) & 1)*8]);
        Bt[p] = su32(&Bs[warp_n*64 + p*16 + (lane & 7) + ((lane >> 3) & 1)*8][64]);
    }

    float acc[2][8][4];
    #pragma unroll
    for (int i = 0; i < 2; i++)
        #pragma unroll
        for (int j = 0; j < 8; j++)
            #pragma unroll
            for (int k = 0; k < 4; k++) acc[i][j][k] = 0.f;

    uint4 rv[9];
    auto load_tile = [&](int m, uint4* rv_) {
        const uint4* Xs  = (const uint4*)(g_Xs + (size_t)m*NN*SROW);
        const __half* Xin = g_Xin + (size_t)m*NN*IROW;
        const __half* Wm  = g_Wg_h + m*128*KP;
        #pragma unroll
        for (int u = 0; u < 9; u++) {
            int idx = tid + u*256;
            if (idx < 1152) {
                int rrow = idx / 9, j = idx - rrow*9;
                uint4 v;
                if (j < 8) v = Xs[(size_t)(n0+rrow)*SV4 + b*8 + j];
                else { v.x = *(const unsigned*)(Xin + (size_t)(n0+rrow)*IROW + b*2);
                       v.y = 0u; v.z = 0u; v.w = 0u; }
                rv_[u] = v;
            } else {
                int i2 = idx - 1152;
                int o = i2 / 9, j = i2 - o*9;
                rv_[u] = *(const uint4*)(Wm + o*KP + 8*j);
            }
        }
    };

    load_tile(0, rv);
    for (int m = 0; m < NMAT; m++) {
        __syncthreads();
        #pragma unroll
        for (int u = 0; u < 9; u++) {
            int idx = tid + u*256;
            if (idx < 1152) { int rrow = idx / 9, j = idx - rrow*9;
                              ((uint4*)&As[rrow][0])[j] = rv[u]; }
            else            { int i2 = idx - 1152; int o = i2 / 9, j = i2 - o*9;
                              ((uint4*)&Bs[o][0])[j] = rv[u]; }
        }
        __syncthreads();
        if (m < NMAT-1) load_tile(m+1, rv);

        #pragma unroll
        for (int ks = 0; ks < 4; ks++) {
            unsigned a0[4], a1[4];
            ldsm4(a0, Au[0] + ks*32);
            ldsm4(a1, Au[1] + ks*32);
            #pragma unroll
            for (int p = 0; p < 4; p++) {
                unsigned bb[4];
                ldsm4(bb, Bu[p] + ks*32);
                mma_16816(acc[0][2*p],   a0, bb);
                mma_16816(acc[0][2*p+1], a0, bb+2);
                mma_16816(acc[1][2*p],   a1, bb);
                mma_16816(acc[1][2*p+1], a1, bb+2);
            }
        }
        {
            unsigned a0[2], a1[2];
            ldsm2(a0, At[0]);
            ldsm2(a1, At[1]);
            #pragma unroll
            for (int p = 0; p < 4; p++) {
                unsigned bt[2];
                ldsm2(bt, Bt[p]);
                mma_1688(acc[0][2*p],   a0, bt[0]);
                mma_1688(acc[0][2*p+1], a0, bt[1]);
                mma_1688(acc[1][2*p],   a1, bt[0]);
                mma_1688(acc[1][2*p+1], a1, bt[1]);
            }
        }
    }

    __half* Xc0 = g_Xs + (size_t)5*NN*SROW;
    #pragma unroll
    for (int mt = 0; mt < 2; mt++) {
        #pragma unroll
        for (int nt = 0; nt < 8; nt++) {
            #pragma unroll
            for (int half_ : {0, 1}) {
                int row_l = warp_m*32 + mt*16 + rr_ + (half_ ? 8 : 0);
                int col   = warp_n*64 + nt*8 + 2*q;
                int n = n0 + row_l;
                float z0 = acc[mt][nt][2*half_+0] + bg[col];
                float z1 = acc[mt][nt][2*half_+1] + bg[col+1];
                float s0 = 1.f/(1.f + expf(-z0));
                float s1 = 1.f/(1.f + expf(-z1));
                if (col < HH) {
                    float2 st = *(const float2*)&state[(size_t)b*NN*HH + (size_t)n*HH + col];
                    __half2 rs = __floats2half2_rn(s0*st.x, s1*st.y);
                    *(__half2*)&Xc0[(size_t)n*SROW + b*HH + col] = rs;
                } else {
                    *(__half2*)&g_U[(size_t)(row0+row_l)*HH + (col-HH)] = __floats2half2_rn(s0, s1);
                }
            }
        }
    }
}

// ---------------- candidate GEMM (pipelined) + GRU combine --------------------
__global__ void __launch_bounds__(256) k_gemm_cand(const float* __restrict__ bc,
                                                   const float* __restrict__ state,
                                                   float* __restrict__ out, int dup)
{
    __shared__ __align__(16) __half As[128][KP];
    __shared__ __align__(16) __half Bs[64][KP];

    int row0 = blockIdx.x * 128;
    int b  = row0 / NN;
    int n0 = row0 - b*NN;
    int tid = threadIdx.x;
    int wid = tid >> 5, lane = tid & 31;
    int q = lane & 3, rr_ = lane >> 2;
    int warp_m = wid & 3, warp_n = wid >> 2;

    unsigned Au[2], At[2], Bu[2], Bt[2];
    #pragma unroll
    for (int mt = 0; mt < 2; mt++) {
        Au[mt] = su32(&As[warp_m*32 + mt*16 + (lane & 15)][(lane >> 4)*8]);
        At[mt] = su32(&As[warp_m*32 + mt*16 + (lane & 15)][64]);
    }
    #pragma unroll
    for (int p = 0; p < 2; p++) {
        Bu[p] = su32(&Bs[warp_n*32 + p*16 + (lane & 7) + ((lane >> 4) & 1)*8][((lane >> 3) & 1)*8]);
        Bt[p] = su32(&Bs[warp_n*32 + p*16 + (lane & 7) + ((lane >> 3) & 1)*8][64]);
    }

    float acc[2][4][4];
    #pragma unroll
    for (int i = 0; i < 2; i++)
        #pragma unroll
        for (int j = 0; j < 4; j++)
            #pragma unroll
            for (int k = 0; k < 4; k++) acc[i][j][k] = 0.f;

    uint4 rv[7];
    auto load_tile = [&](int m, uint4* rv_) {
        const uint4* Xs  = (const uint4*)(g_Xs + (size_t)(5+m)*NN*SROW);
        const __half* Xin = g_Xin + (size_t)m*NN*IROW;
        const __half* Wm  = g_Wc_h + m*64*KP;
        #pragma unroll
        for (int u = 0; u < 7; u++) {
            int idx = tid + u*256;
            if (idx < 1152) {
                int rrow = idx / 9, j = idx - rrow*9;
                uint4 v;
                if (j < 8) v = Xs[(size_t)(n0+rrow)*SV4 + b*8 + j];
                else { v.x = *(const unsigned*)(Xin + (size_t)(n0+rrow)*IROW + b*2);
                       v.y = 0u; v.z = 0u; v.w = 0u; }
                rv_[u] = v;
            } else if (idx < 1728) {
                int i2 = idx - 1152;
                int o = i2 / 9, j = i2 - o*9;
                rv_[u] = *(const uint4*)(Wm + o*KP + 8*j);
            }
        }
    };

    load_tile(0, rv);
    for (int m = 0; m < NMAT; m++) {
        __syncthreads();
        #pragma unroll
        for (int u = 0; u < 7; u++) {
            int idx = tid + u*256;
            if (idx < 1152) { int rrow = idx / 9, j = idx - rrow*9;
                              ((uint4*)&As[rrow][0])[j] = rv[u]; }
            else if (idx < 1728) { int i2 = idx - 1152; int o = i2 / 9, j = i2 - o*9;
                                   ((uint4*)&Bs[o][0])[j] = rv[u]; }
        }
        __syncthreads();
        if (m < NMAT-1) load_tile(m+1, rv);

        #pragma unroll
        for (int ks = 0; ks < 4; ks++) {
            unsigned a0[4], a1[4];
            ldsm4(a0, Au[0] + ks*32);
            ldsm4(a1, Au[1] + ks*32);
            #pragma unroll
            for (int p = 0; p < 2; p++) {
                unsigned bb[4];
                ldsm4(bb, Bu[p] + ks*32);
                mma_16816(acc[0][2*p],   a0, bb);
                mma_16816(acc[0][2*p+1], a0, bb+2);
                mma_16816(acc[1][2*p],   a1, bb);
                mma_16816(acc[1][2*p+1], a1, bb+2);
            }
        }
        {
            unsigned a0[2], a1[2];
            ldsm2(a0, At[0]);
            ldsm2(a1, At[1]);
            #pragma unroll
            for (int p = 0; p < 2; p++) {
                unsigned bt[2];
                ldsm2(bt, Bt[p]);
                mma_1688(acc[0][2*p],   a0, bt[0]);
                mma_1688(acc[0][2*p+1], a0, bt[1]);
                mma_1688(acc[1][2*p],   a1, bt[0]);
                mma_1688(acc[1][2*p+1], a1, bt[1]);
            }
        }
    }

    #pragma unroll
    for (int mt = 0; mt < 2; mt++) {
        #pragma unroll
        for (int nt = 0; nt < 4; nt++) {
            #pragma unroll
            for (int half_ : {0, 1}) {
                int row_l = warp_m*32 + mt*16 + rr_ + (half_ ? 8 : 0);
                int col   = warp_n*32 + nt*8 + 2*q;
                int n = n0 + row_l;
                int row = row0 + row_l;
                float c0 = tanhf(acc[mt][nt][2*half_+0] + bc[col]);
                float c1 = tanhf(acc[mt][nt][2*half_+1] + bc[col+1]);
                size_t sidx = (size_t)b*NN*HH + (size_t)n*HH + col;
                float2 u  = __half22float2(*(const __half2*)&g_U[(size_t)row*HH + col]);
                float2 st = *(const float2*)&state[sidx];
                float2 ns;
                ns.x = u.x*st.x + (1.f - u.x)*c0;
                ns.y = u.y*st.y + (1.f - u.y)*c1;
                *(float2*)&out[sidx] = ns;
                if (dup) *(float2*)&out[sidx + (size_t)BB*NN*HH] = ns;
            }
        }
    }
}

// ---------------- launch ------------------------------------------------------
extern "C" void kernel_launch(void* const* d_in, const int* in_sizes, int n_in,
                              void* d_out, int out_size)
{
    const float* inputs = (const float*)d_in[0];
    const float* state  = (const float*)d_in[1];
    const int*   esrc   = (const int*)  d_in[2];
    const int*   edst   = (const int*)  d_in[3];
    const float* v1     = (const float*)d_in[4];
    const float* v2     = (const float*)d_in[5];
    const float* Wg     = (const float*)d_in[6];
    const float* bg     = (const float*)d_in[7];
    const float* Wc     = (const float*)d_in[8];
    const float* bc     = (const float*)d_in[9];
    float* out = (float*)d_out;
    int dup = (out_size >= 2*BB*NN*HH) ? 1 : 0;

    k_count_init<<<CNT_BLKS + INIT_BLKS, 256>>>(esrc, edst, inputs, state, Wg, Wc);
    k_scatter<<<EE/4/256, 256>>>(esrc, edst);
    k_sortfill<<<dim3(NN/8,2), 256>>>(esrc, edst, v1, v2);   // also re-zeros cnt/cur

    k_spmm<<<dim3(NN+INBLK,2), 128>>>(0,1, 0,3);
    k_spmm<<<dim3(NN+INBLK,2), 128>>>(1,2, 3,4);

    k_gemm_gate<<<(BB*NN)/128, 256>>>(bg, state);

    k_spmm<<<dim3(NN,2), 128>>>(5,6, 5,8);
    k_spmm<<<dim3(NN,2), 128>>>(6,7, 8,9);

    k_gemm_cand<<<(BB*NN)/128, 256>>>(bc, state, out, dup);
}

// round 16
// speedup vs baseline: 1.0988x; 1.0988x over previous
#include <cuda_runtime.h>
#include <cuda_fp16.h>
#include <math.h>

#define NN   8192
#define BB   16
#define IND  2
#define HH   64
#define FF   66
#define EE   131072
#define NMAT 5
#define KP   72
#define SROW 1024     // 16 batches * 64 halves = 2048 B
#define SV4  128      // uint4 per state row
#define IROW 32       // 16 batches * 2 halves = 64 B
#define INBLK (NN/32)
#define CNT_BLKS (EE/4/256)
// init work in uint4 (8-half) units
#define I_T1 ((size_t)NN*SROW/8)
#define I_T2 (I_T1 + (size_t)NN*IROW/8)
#define I_T3 (I_T2 + (size_t)NMAT*128*KP/8)
#define I_T4 (I_T3 + (size_t)NMAT*64*KP/8)
#define INIT_BLKS ((unsigned)((I_T4 + 255)/256))
// GEMM dynamic smem: double-buffered tiles, row stride 144 B (72 halves)
#define A_STAGE 18432              // 128 rows * 144 B
#define BG_STAGE 18432             // 128 o
#define BC_STAGE 9216              // 64 o
#define GATE_SMEM (2*A_STAGE + 2*BG_STAGE)   // 73728
#define CAND_SMEM (2*A_STAGE + 2*BC_STAGE)   // 55296

// ---------------- device scratch (static; zero-initialized at load) ----------
__device__ __half g_Xs[(size_t)10*NN*SROW];
__device__ __half g_Xin[(size_t)5*NN*IROW];
__device__ __half g_U[(size_t)BB*NN*HH];
__device__ __half g_Wg_h[NMAT*128*KP];
__device__ __half g_Wc_h[NMAT*64*KP];
__device__ int   g_cnt[2][NN];
__device__ int   g_cur[2][NN];
__device__ int   g_ptr[2][NN+1];
__device__ int   g_eidx[2][EE];
__device__ int2  g_cw[2][EE];
__device__ int   g_done;

// ---------------- helpers ------------------------------------------------------
__device__ __forceinline__ unsigned su32(const void* p) {
    return (unsigned)__cvta_generic_to_shared(p);
}
#define CPA16(d, s)  asm volatile("cp.async.ca.shared.global [%0], [%1], 16;" :: "r"(d), "l"(__cvta_generic_to_global(s)) : "memory")
#define CPC()        asm volatile("cp.async.commit_group;" ::: "memory")
#define CPW1()       asm volatile("cp.async.wait_group 1;" ::: "memory")
#define CPW0()       asm volatile("cp.async.wait_group 0;" ::: "memory")

__device__ __forceinline__ uint4 pack8(const float* a)
{
    __half2 a0 = __floats2half2_rn(a[0],a[1]);
    __half2 a1 = __floats2half2_rn(a[2],a[3]);
    __half2 a2 = __floats2half2_rn(a[4],a[5]);
    __half2 a3 = __floats2half2_rn(a[6],a[7]);
    uint4 st; st.x=*(unsigned*)&a0; st.y=*(unsigned*)&a1; st.z=*(unsigned*)&a2; st.w=*(unsigned*)&a3;
    return st;
}

// ---------------- fused count + init (8x vectorized) + last-block scan --------
__global__ void k_count_init(const int* __restrict__ src, const int* __restrict__ dst,
                             const float* __restrict__ inputs, const float* __restrict__ state,
                             const float* __restrict__ Wg, const float* __restrict__ Wc)
{
    if (blockIdx.x < CNT_BLKS) {
        int e4 = blockIdx.x*blockDim.x + threadIdx.x;
        int4 s = __ldg((const int4*)src + e4);
        int4 d = __ldg((const int4*)dst + e4);
        atomicAdd(&g_cnt[0][s.x], 1); atomicAdd(&g_cnt[0][s.y], 1);
        atomicAdd(&g_cnt[0][s.z], 1); atomicAdd(&g_cnt[0][s.w], 1);
        atomicAdd(&g_cnt[1][d.x], 1); atomicAdd(&g_cnt[1][d.y], 1);
        atomicAdd(&g_cnt[1][d.z], 1); atomicAdd(&g_cnt[1][d.w], 1);

        __threadfence();
        __syncthreads();
        __shared__ int ticket;
        if (threadIdx.x == 0) ticket = atomicAdd(&g_done, 1);
        __syncthreads();
        if (ticket != CNT_BLKS-1) return;

        __shared__ int wsum[8];
        int tid = threadIdx.x, lane = tid & 31, wrp = tid >> 5;
        for (int m = 0; m < 2; m++) {
            int base = tid*32;
            int c[32];
            int s_local = 0;
            #pragma unroll
            for (int j = 0; j < 32; j++) { c[j] = __ldcg(&g_cnt[m][base+j]); s_local += c[j]; }
            int v = s_local;
            #pragma unroll
            for (int off = 1; off < 32; off <<= 1) {
                int o = __shfl_up_sync(0xffffffffu, v, off);
                if (lane >= off) v += o;
            }
            if (lane == 31) wsum[wrp] = v;
            __syncthreads();
            if (wrp == 0) {
                int w = (lane < 8) ? wsum[lane] : 0;
                #pragma unroll
                for (int off = 1; off < 8; off <<= 1) {
                    int o = __shfl_up_sync(0xffffffffu, w, off);
                    if (lane >= off) w += o;
                }
                if (lane < 8) wsum[lane] = w;
            }
            __syncthreads();
            int run = v - s_local + (wrp ? wsum[wrp-1] : 0);
            #pragma unroll
            for (int j = 0; j < 32; j++) { g_ptr[m][base+j] = run; run += c[j]; }
            if (tid == 255) g_ptr[m][NN] = run;
            __syncthreads();
        }
        if (tid == 0) g_done = 0;
        return;
    }

    size_t idx = (size_t)(blockIdx.x - CNT_BLKS)*blockDim.x + threadIdx.x;
    if (idx < I_T1) {
        size_t h8 = idx*8;
        int n = (int)(h8 / SROW);
        int c = (int)(h8 - (size_t)n*SROW);
        int b = c >> 6, h0 = c & 63;
        const float4* sp = (const float4*)(state + (size_t)b*NN*HH + (size_t)n*HH + h0);
        float4 f0 = __ldg(sp), f1 = __ldg(sp+1);
        float v[8] = {f0.x,f0.y,f0.z,f0.w,f1.x,f1.y,f1.z,f1.w};
        ((uint4*)g_Xs)[idx] = pack8(v);
    } else if (idx < I_T2) {
        size_t i8 = (idx - I_T1)*8;
        int n = (int)(i8 / IROW);
        int c0 = (int)(i8 - (size_t)n*IROW);
        int b0 = c0 >> 1;
        float v[8];
        #pragma unroll
        for (int u = 0; u < 4; u++) {
            float2 p = *(const float2*)(inputs + (size_t)(b0+u)*NN*IND + (size_t)n*IND);
            v[2*u] = p.x; v[2*u+1] = p.y;
        }
        ((uint4*)g_Xin)[idx - I_T1] = pack8(v);
    } else if (idx < I_T3) {
        size_t i8 = (idx - I_T2)*8;
        int m = (int)(i8 / (128*KP));
        int rem = (int)(i8 - (size_t)m*(128*KP));
        int o = rem / KP, k0 = rem - o*KP;
        float v[8];
        #pragma unroll
        for (int u = 0; u < 8; u++) {
            int k = k0 + u;
            float w = 0.f;
            if (k < 66) {
                int f = (k < 64) ? (k + IND) : (k - 64);
                const float* base = Wg + (size_t)(f*NMAT)*128 + o;
                if      (m == 0) w = base[0] - base[2*128] - base[4*128];
                else if (m == 2) w = 2.f*base[2*128];
                else if (m == 4) w = 2.f*base[4*128];
                else             w = base[m*128];
            }
            v[u] = w;
        }
        ((uint4*)g_Wg_h)[idx - I_T2] = pack8(v);
    } else if (idx < I_T4) {
        size_t i8 = (idx - I_T3)*8;
        int m = (int)(i8 / (64*KP));
        int rem = (int)(i8 - (size_t)m*(64*KP));
        int o = rem / KP, k0 = rem - o*KP;
        float v[8];
        #pragma unroll
        for (int u = 0; u < 8; u++) {
            int k = k0 + u;
            float w = 0.f;
            if (k < 66) {
                int f = (k < 64) ? (k + IND) : (k - 64);
                const float* base = Wc + (size_t)(f*NMAT)*64 + o;
                if      (m == 0) w = base[0] - base[2*64] - base[4*64];
                else if (m == 2) w = 2.f*base[2*64];
                else if (m == 4) w = 2.f*base[4*64];
                else             w = base[m*64];
            }
            v[u] = w;
        }
        ((uint4*)g_Wc_h)[idx - I_T3] = pack8(v);
    }
}

__global__ void k_scatter(const int* __restrict__ src, const int* __restrict__ dst)
{
    int e4 = blockIdx.x*blockDim.x + threadIdx.x;
    if (e4 < EE/4) {
        int4 s = __ldg((const int4*)src + e4);
        int4 d = __ldg((const int4*)dst + e4);
        int e = e4*4;
        int p;
        p = g_ptr[0][s.x] + atomicAdd(&g_cur[0][s.x], 1); g_eidx[0][p] = e;
        p = g_ptr[0][s.y] + atomicAdd(&g_cur[0][s.y], 1); g_eidx[0][p] = e+1;
        p = g_ptr[0][s.z] + atomicAdd(&g_cur[0][s.z], 1); g_eidx[0][p] = e+2;
        p = g_ptr[0][s.w] + atomicAdd(&g_cur[0][s.w], 1); g_eidx[0][p] = e+3;
        p = g_ptr[1][d.x] + atomicAdd(&g_cur[1][d.x], 1); g_eidx[1][p] = e;
        p = g_ptr[1][d.y] + atomicAdd(&g_cur[1][d.y], 1); g_eidx[1][p] = e+1;
        p = g_ptr[1][d.z] + atomicAdd(&g_cur[1][d.z], 1); g_eidx[1][p] = e+2;
        p = g_ptr[1][d.w] + atomicAdd(&g_cur[1][d.w], 1); g_eidx[1][p] = e+3;
    }
}

// ---- warp-per-row bitonic sort (64 elems) + fill + counter cleanup -----------
__global__ void k_sortfill(const int* __restrict__ src, const int* __restrict__ dst,
                           const float* __restrict__ v1, const float* __restrict__ v2)
{
    int m    = blockIdx.y;
    int wrp  = threadIdx.x >> 5;
    int lane = threadIdx.x & 31;
    int r    = blockIdx.x*8 + wrp;
    if (r >= NN) return;
    int beg = g_ptr[m][r], end = g_ptr[m][r+1];
    int deg = end - beg;

    if (lane == 0) { g_cnt[m][r] = 0; g_cur[m][r] = 0; }

    if (deg <= 64) {
        const int BIG = 0x7fffffff;
        int e0 = (lane      < deg) ? g_eidx[m][beg + lane]      : BIG;
        int e1 = (lane + 32 < deg) ? g_eidx[m][beg + lane + 32] : BIG;

        #pragma unroll
        for (int k = 2; k <= 64; k <<= 1) {
            #pragma unroll
            for (int j = k >> 1; j > 0; j >>= 1) {
                if (j == 32) {
                    int lo = min(e0, e1), hi = max(e0, e1);
                    e0 = lo; e1 = hi;
                } else {
                    int p0 = __shfl_xor_sync(0xffffffffu, e0, j);
                    bool up0 = ((lane & k) == 0) || (k == 64);
                    bool km0 = (((lane & j) == 0) == up0);
                    e0 = km0 ? min(e0, p0) : max(e0, p0);
                    int p1 = __shfl_xor_sync(0xffffffffu, e1, j);
                    bool up1 = (k == 64) || (((lane + 32) & k) == 0);
                    bool km1 = (((lane & j) == 0) == up1);
                    e1 = km1 ? min(e1, p1) : max(e1, p1);
                }
            }
        }
        if (lane < deg) {
            int e = e0;
            int2 cw;
            if (m == 0) { cw.x = __ldg(dst+e); cw.y = __float_as_int(__ldg(v1+e)); }
            else        { cw.x = __ldg(src+e); cw.y = __float_as_int(__ldg(v2+e)); }
            g_cw[m][beg + lane] = cw;
        }
        if (lane + 32 < deg) {
            int e = e1;
            int2 cw;
            if (m == 0) { cw.x = __ldg(dst+e); cw.y = __float_as_int(__ldg(v1+e)); }
            else        { cw.x = __ldg(src+e); cw.y = __float_as_int(__ldg(v2+e)); }
            g_cw[m][beg + lane + 32] = cw;
        }
    } else if (lane == 0) {
        for (int i = beg+1; i < end; i++) {
            int key = g_eidx[m][i];
            int j = i-1;
            while (j >= beg && g_eidx[m][j] > key) { g_eidx[m][j+1] = g_eidx[m][j]; j--; }
            g_eidx[m][j+1] = key;
        }
        for (int i = beg; i < end; i++) {
            int e = g_eidx[m][i];
            int2 cw;
            if (m == 0) { cw.x = dst[e]; cw.y = __float_as_int(v1[e]); }
            else        { cw.x = src[e]; cw.y = __float_as_int(v2[e]); }
            g_cw[m][i] = cw;
        }
    }
}

// ---------------- SPMM (R12-proven shape) -------------------------------------
__device__ __forceinline__ void acc8(float* a, float w, uint4 h)
{
    float2 p0 = __half22float2(*(const __half2*)&h.x);
    float2 p1 = __half22float2(*(const __half2*)&h.y);
    float2 p2 = __half22float2(*(const __half2*)&h.z);
    float2 p3 = __half22float2(*(const __half2*)&h.w);
    a[0] += w*p0.x; a[1] += w*p0.y; a[2] += w*p1.x; a[3] += w*p1.y;
    a[4] += w*p2.x; a[5] += w*p2.y; a[6] += w*p3.x; a[7] += w*p3.y;
}

__global__ void __launch_bounds__(128) k_spmm(int xiA,int yiA,int xiB,int yiB)
{
    int m  = blockIdx.y;
    int xi = m ? xiB : xiA;
    int yi = m ? yiB : yiA;
    const int2* __restrict__ cw = g_cw[m];

    if (blockIdx.x < NN) {
        const uint4* __restrict__ X = (const uint4*)(g_Xs + (size_t)xi*NN*SROW);
        uint4*       __restrict__ Y = (uint4*)      (g_Xs + (size_t)yi*NN*SROW);
        int r = blockIdx.x;
        int t = threadIdx.x;
        int beg = g_ptr[m][r], end = g_ptr[m][r+1];

        float acc[8] = {0.f,0.f,0.f,0.f,0.f,0.f,0.f,0.f};
        int j = beg;
        for (; j + 8 <= end; j += 8) {
            int2 e[8];
            #pragma unroll
            for (int u = 0; u < 8; u++) e[u] = __ldg(cw + j + u);
            uint4 h[8];
            #pragma unroll
            for (int u = 0; u < 8; u++) h[u] = __ldg(X + (size_t)e[u].x*SV4 + t);
            #pragma unroll
            for (int u = 0; u < 8; u++) acc8(acc, __int_as_float(e[u].y), h[u]);
        }
        for (; j < end; j++) {
            int2 e = __ldg(cw + j);
            uint4 h = __ldg(X + (size_t)e.x*SV4 + t);
            acc8(acc, __int_as_float(e.y), h);
        }
        Y[(size_t)r*SV4 + t] = pack8(acc);
    } else {
        const uint4* __restrict__ X = (const uint4*)(g_Xin + (size_t)xi*NN*IROW);
        uint4*       __restrict__ Y = (uint4*)      (g_Xin + (size_t)yi*NN*IROW);
        int r = (blockIdx.x - NN)*32 + (threadIdx.x >> 2);
        int q = threadIdx.x & 3;
        int beg = g_ptr[m][r], end = g_ptr[m][r+1];
        float acc[8] = {0.f,0.f,0.f,0.f,0.f,0.f,0.f,0.f};
        for (int j = beg; j < end; j++) {
            int2 e = __ldg(cw + j);
            uint4 h = __ldg(X + (size_t)e.x*4 + q);
            acc8(acc, __int_as_float(e.y), h);
        }
        Y[(size_t)r*4 + q] = pack8(acc);
    }
}

// ---------------- MMA / ldmatrix helpers --------------------------------------
__device__ __forceinline__ void mma_16816(float c[4], const unsigned a[4], const unsigned b[2]) {
    asm volatile(
        "mma.sync.aligned.m16n8k16.row.col.f32.f16.f16.f32 "
        "{%0,%1,%2,%3},{%4,%5,%6,%7},{%8,%9},{%0,%1,%2,%3};\n"
        : "+f"(c[0]), "+f"(c[1]), "+f"(c[2]), "+f"(c[3])
        : "r"(a[0]), "r"(a[1]), "r"(a[2]), "r"(a[3]), "r"(b[0]), "r"(b[1]));
}
__device__ __forceinline__ void mma_1688(float c[4], const unsigned a[2], const unsigned b0) {
    asm volatile(
        "mma.sync.aligned.m16n8k8.row.col.f32.f16.f16.f32 "
        "{%0,%1,%2,%3},{%4,%5},{%6},{%0,%1,%2,%3};\n"
        : "+f"(c[0]), "+f"(c[1]), "+f"(c[2]), "+f"(c[3])
        : "r"(a[0]), "r"(a[1]), "r"(b0));
}
__device__ __forceinline__ void ldsm4(unsigned* r, unsigned a) {
    asm volatile("ldmatrix.sync.aligned.m8n8.x4.shared.b16 {%0,%1,%2,%3},[%4];"
        : "=r"(r[0]),"=r"(r[1]),"=r"(r[2]),"=r"(r[3]) : "r"(a));
}
__device__ __forceinline__ void ldsm2(unsigned* r, unsigned a) {
    asm volatile("ldmatrix.sync.aligned.m8n8.x2.shared.b16 {%0,%1},[%2];"
        : "=r"(r[0]),"=r"(r[1]) : "r"(a));
}

// ---- gate GEMM: cp.async double-buffered tiles + fused gating -----------------
__global__ void __launch_bounds__(256) k_gemm_gate(const float* __restrict__ bg,
                                                   const float* __restrict__ state)
{
    extern __shared__ __align__(16) char dsm[];
    unsigned sA0 = su32(dsm);
    unsigned sB0 = sA0 + 2*A_STAGE;

    int row0 = blockIdx.x * 128;
    int b  = row0 / NN;
    int n0 = row0 - b*NN;
    int tid = threadIdx.x;
    int wid = tid >> 5, lane = tid & 31;
    int q = lane & 3, rr_ = lane >> 2;
    int warp_m = wid & 3, warp_n = wid >> 2;

    unsigned Au[2], At[2], Bu[4], Bt[4];
    #pragma unroll
    for (int mt = 0; mt < 2; mt++) {
        int row = warp_m*32 + mt*16 + (lane & 15);
        Au[mt] = sA0 + row*144 + ((lane >> 4)*8)*2;
        At[mt] = sA0 + row*144 + 128;
    }
    #pragma unroll
    for (int p = 0; p < 4; p++) {
        int o1 = warp_n*64 + p*16 + (lane & 7) + ((lane >> 4) & 1)*8;
        int o2 = warp_n*64 + p*16 + (lane & 7) + ((lane >> 3) & 1)*8;
        Bu[p] = sB0 + o1*144 + (((lane >> 3) & 1)*8)*2;
        Bt[p] = sB0 + o2*144 + 128;
    }

    float acc[2][8][4];
    #pragma unroll
    for (int i = 0; i < 2; i++)
        #pragma unroll
        for (int j = 0; j < 8; j++)
            #pragma unroll
            for (int k = 0; k < 4; k++) acc[i][j][k] = 0.f;

    auto fill_tile = [&](int m, int stage) {
        const uint4* Xs  = (const uint4*)(g_Xs + (size_t)m*NN*SROW);
        const __half* Xin = g_Xin + (size_t)m*NN*IROW;
        const __half* Wm  = g_Wg_h + m*128*KP;
        unsigned dA = sA0 + stage*A_STAGE;
        unsigned dB = sB0 + stage*BG_STAGE;
        char* pA = dsm + stage*A_STAGE;
        for (int idx = tid; idx < 1152; idx += 256) {
            int rr = idx / 9, j = idx - rr*9;
            if (j < 8) {
                CPA16(dA + rr*144 + j*16, &Xs[(size_t)(n0+rr)*SV4 + b*8 + j]);
            } else {
                // 4-byte fragment: plain LDG + zero-padded STS (src not 16B-aligned)
                unsigned xv = *(const unsigned*)(Xin + (size_t)(n0+rr)*IROW + b*2);
                uint4 v; v.x = xv; v.y = 0u; v.z = 0u; v.w = 0u;
                *(uint4*)(pA + rr*144 + 128) = v;
            }
        }
        for (int idx = tid; idx < 1152; idx += 256) {
            int o = idx / 9, j = idx - o*9;
            CPA16(dB + o*144 + j*16, Wm + o*KP + 8*j);
        }
        CPC();
    };

    fill_tile(0, 0);
    for (int m = 0; m < NMAT; m++) {
        int stage = m & 1;
        if (m < NMAT-1) { fill_tile(m+1, stage ^ 1); CPW1(); }
        else            { CPW0(); }
        __syncthreads();
        unsigned so = stage*A_STAGE;   // A and B stage strides are equal (18432)

        #pragma unroll
        for (int ks = 0; ks < 4; ks++) {
            unsigned a0[4], a1[4];
            ldsm4(a0, Au[0] + so + ks*32);
            ldsm4(a1, Au[1] + so + ks*32);
            #pragma unroll
            for (int p = 0; p < 4; p++) {
                unsigned bb[4];
                ldsm4(bb, Bu[p] + so + ks*32);
                mma_16816(acc[0][2*p],   a0, bb);
                mma_16816(acc[0][2*p+1], a0, bb+2);
                mma_16816(acc[1][2*p],   a1, bb);
                mma_16816(acc[1][2*p+1], a1, bb+2);
            }
        }
        {
            unsigned a0[2], a1[2];
            ldsm2(a0, At[0] + so);
            ldsm2(a1, At[1] + so);
            #pragma unroll
            for (int p = 0; p < 4; p++) {
                unsigned bt[2];
                ldsm2(bt, Bt[p] + so);
                mma_1688(acc[0][2*p],   a0, bt[0]);
                mma_1688(acc[0][2*p+1], a0, bt[1]);
                mma_1688(acc[1][2*p],   a1, bt[0]);
                mma_1688(acc[1][2*p+1], a1, bt[1]);
            }
        }
        __syncthreads();
    }

    __half* Xc0 = g_Xs + (size_t)5*NN*SROW;
    #pragma unroll
    for (int mt = 0; mt < 2; mt++) {
        #pragma unroll
        for (int nt = 0; nt < 8; nt++) {
            #pragma unroll
            for (int half_ : {0, 1}) {
                int row_l = warp_m*32 + mt*16 + rr_ + (half_ ? 8 : 0);
                int col   = warp_n*64 + nt*8 + 2*q;
                int n = n0 + row_l;
                float z0 = acc[mt][nt][2*half_+0] + bg[col];
                float z1 = acc[mt][nt][2*half_+1] + bg[col+1];
                float s0 = 1.f/(1.f + expf(-z0));
                float s1 = 1.f/(1.f + expf(-z1));
                if (col < HH) {
                    float2 st = *(const float2*)&state[(size_t)b*NN*HH + (size_t)n*HH + col];
                    *(__half2*)&Xc0[(size_t)n*SROW + b*HH + col] = __floats2half2_rn(s0*st.x, s1*st.y);
                } else {
                    *(__half2*)&g_U[(size_t)(row0+row_l)*HH + (col-HH)] = __floats2half2_rn(s0, s1);
                }
            }
        }
    }
}

// ---- candidate GEMM: cp.async double-buffered + GRU combine -------------------
__global__ void __launch_bounds__(256) k_gemm_cand(const float* __restrict__ bc,
                                                   const float* __restrict__ state,
                                                   float* __restrict__ out, int dup)
{
    extern __shared__ __align__(16) char dsm[];
    unsigned sA0 = su32(dsm);
    unsigned sB0 = sA0 + 2*A_STAGE;

    int row0 = blockIdx.x * 128;
    int b  = row0 / NN;
    int n0 = row0 - b*NN;
    int tid = threadIdx.x;
    int wid = tid >> 5, lane = tid & 31;
    int q = lane & 3, rr_ = lane >> 2;
    int warp_m = wid & 3, warp_n = wid >> 2;

    unsigned Au[2], At[2], Bu[2], Bt[2];
    #pragma unroll
    for (int mt = 0; mt < 2; mt++) {
        int row = warp_m*32 + mt*16 + (lane & 15);
        Au[mt] = sA0 + row*144 + ((lane >> 4)*8)*2;
        At[mt] = sA0 + row*144 + 128;
    }
    #pragma unroll
    for (int p = 0; p < 2; p++) {
        int o1 = warp_n*32 + p*16 + (lane & 7) + ((lane >> 4) & 1)*8;
        int o2 = warp_n*32 + p*16 + (lane & 7) + ((lane >> 3) & 1)*8;
        Bu[p] = sB0 + o1*144 + (((lane >> 3) & 1)*8)*2;
        Bt[p] = sB0 + o2*144 + 128;
    }

    float acc[2][4][4];
    #pragma unroll
    for (int i = 0; i < 2; i++)
        #pragma unroll
        for (int j = 0; j < 4; j++)
            #pragma unroll
            for (int k = 0; k < 4; k++) acc[i][j][k] = 0.f;

    auto fill_tile = [&](int m, int stage) {
        const uint4* Xs  = (const uint4*)(g_Xs + (size_t)(5+m)*NN*SROW);
        const __half* Xin = g_Xin + (size_t)m*NN*IROW;
        const __half* Wm  = g_Wc_h + m*64*KP;
        unsigned dA = sA0 + stage*A_STAGE;
        unsigned dB = sB0 + stage*BC_STAGE;
        char* pA = dsm + stage*A_STAGE;
        for (int idx = tid; idx < 1152; idx += 256) {
            int rr = idx / 9, j = idx - rr*9;
            if (j < 8) {
                CPA16(dA + rr*144 + j*16, &Xs[(size_t)(n0+rr)*SV4 + b*8 + j]);
            } else {
                unsigned xv = *(const unsigned*)(Xin + (size_t)(n0+rr)*IROW + b*2);
                uint4 v; v.x = xv; v.y = 0u; v.z = 0u; v.w = 0u;
                *(uint4*)(pA + rr*144 + 128) = v;
            }
        }
        for (int idx = tid; idx < 576; idx += 256) {
            int o = idx / 9, j = idx - o*9;
            CPA16(dB + o*144 + j*16, Wm + o*KP + 8*j);
        }
        CPC();
    };

    fill_tile(0, 0);
    for (int m = 0; m < NMAT; m++) {
        int stage = m & 1;
        if (m < NMAT-1) { fill_tile(m+1, stage ^ 1); CPW1(); }
        else            { CPW0(); }
        __syncthreads();
        unsigned soA = stage*A_STAGE;
        unsigned soB = stage*BC_STAGE;

        #pragma unroll
        for (int ks = 0; ks < 4; ks++) {
            unsigned a0[4], a1[4];
            ldsm4(a0, Au[0] + soA + ks*32);
            ldsm4(a1, Au[1] + soA + ks*32);
            #pragma unroll
            for (int p = 0; p < 2; p++) {
                unsigned bb[4];
                ldsm4(bb, Bu[p] + soB + ks*32);
                mma_16816(acc[0][2*p],   a0, bb);
                mma_16816(acc[0][2*p+1], a0, bb+2);
                mma_16816(acc[1][2*p],   a1, bb);
                mma_16816(acc[1][2*p+1], a1, bb+2);
            }
        }
        {
            unsigned a0[2], a1[2];
            ldsm2(a0, At[0] + soA);
            ldsm2(a1, At[1] + soA);
            #pragma unroll
            for (int p = 0; p < 2; p++) {
                unsigned bt[2];
                ldsm2(bt, Bt[p] + soB);
                mma_1688(acc[0][2*p],   a0, bt[0]);
                mma_1688(acc[0][2*p+1], a0, bt[1]);
                mma_1688(acc[1][2*p],   a1, bt[0]);
                mma_1688(acc[1][2*p+1], a1, bt[1]);
            }
        }
        __syncthreads();
    }

    #pragma unroll
    for (int mt = 0; mt < 2; mt++) {
        #pragma unroll
        for (int nt = 0; nt < 4; nt++) {
            #pragma unroll
            for (int half_ : {0, 1}) {
                int row_l = warp_m*32 + mt*16 + rr_ + (half_ ? 8 : 0);
                int col   = warp_n*32 + nt*8 + 2*q;
                int n = n0 + row_l;
                int row = row0 + row_l;
                float c0 = tanhf(acc[mt][nt][2*half_+0] + bc[col]);
                float c1 = tanhf(acc[mt][nt][2*half_+1] + bc[col+1]);
                size_t sidx = (size_t)b*NN*HH + (size_t)n*HH + col;
                float2 u  = __half22float2(*(const __half2*)&g_U[(size_t)row*HH + col]);
                float2 st = *(const float2*)&state[sidx];
                float2 ns;
                ns.x = u.x*st.x + (1.f - u.x)*c0;
                ns.y = u.y*st.y + (1.f - u.y)*c1;
                *(float2*)&out[sidx] = ns;
                if (dup) *(float2*)&out[sidx + (size_t)BB*NN*HH] = ns;
            }
        }
    }
}

// ---------------- launch ------------------------------------------------------
extern "C" void kernel_launch(void* const* d_in, const int* in_sizes, int n_in,
                              void* d_out, int out_size)
{
    const float* inputs = (const float*)d_in[0];
    const float* state  = (const float*)d_in[1];
    const int*   esrc   = (const int*)  d_in[2];
    const int*   edst   = (const int*)  d_in[3];
    const float* v1     = (const float*)d_in[4];
    const float* v2     = (const float*)d_in[5];
    const float* Wg     = (const float*)d_in[6];
    const float* bg     = (const float*)d_in[7];
    const float* Wc     = (const float*)d_in[8];
    const float* bc     = (const float*)d_in[9];
    float* out = (float*)d_out;
    int dup = (out_size >= 2*BB*NN*HH) ? 1 : 0;

    cudaFuncSetAttribute(k_gemm_gate, cudaFuncAttributeMaxDynamicSharedMemorySize, GATE_SMEM);
    cudaFuncSetAttribute(k_gemm_cand, cudaFuncAttributeMaxDynamicSharedMemorySize, CAND_SMEM);

    k_count_init<<<CNT_BLKS + INIT_BLKS, 256>>>(esrc, edst, inputs, state, Wg, Wc);
    k_scatter<<<EE/4/256, 256>>>(esrc, edst);
    k_sortfill<<<dim3(NN/8,2), 256>>>(esrc, edst, v1, v2);

    k_spmm<<<dim3(NN+INBLK,2), 128>>>(0,1, 0,3);
    k_spmm<<<dim3(NN+INBLK,2), 128>>>(1,2, 3,4);

    k_gemm_gate<<<(BB*NN)/128, 256, GATE_SMEM>>>(bg, state);

    k_spmm<<<dim3(NN,2), 128>>>(5,6, 5,8);
    k_spmm<<<dim3(NN,2), 128>>>(6,7, 8,9);

    k_gemm_cand<<<(BB*NN)/128, 256, CAND_SMEM>>>(bc, state, out, dup);
}